// round 11
// baseline (speedup 1.0000x reference)
#include <cuda_runtime.h>
#include <cuda_fp16.h>
#include <mma.h>
#include <cstdint>

using namespace nvcuda;

#define NN 8192
#define CC 256

// ---------------------------------------------------------------------------
// Scratch (__device__ globals; allocation-free rule)
// ---------------------------------------------------------------------------
__device__ float  g_s[NN];                       // d^{-1/2}
__device__ __half g_adjh[(size_t)NN * NN];       // fp16(adj)
__device__ __half g_xsh[NN * CC];                // fp16(s_j * x[j][n])  [K][N]
__device__ __half g_a2h[NN * CC];                // fp16(s_i*(t + s_i*x)) [M][K]
__device__ __half g_wh[CC * CC];                 // fp16(w)  [K][N]
__device__ int    g_done[64];                    // per-row-tile arrival counter

// ---------------------------------------------------------------------------
__device__ __forceinline__ uint32_t smem_u32(const void* p) {
    uint32_t a;
    asm("{ .reg .u64 t; cvta.to.shared.u64 t, %1; cvt.u32.u64 %0, t; }" : "=r"(a) : "l"(p));
    return a;
}
__device__ __forceinline__ void cpa16(uint32_t s, const void* g) {
    asm volatile("cp.async.cg.shared.global [%0], [%1], 16;" :: "r"(s), "l"(g));
}
#define CP_COMMIT() asm volatile("cp.async.commit_group;" ::: "memory")
#define CP_WAIT_2() asm volatile("cp.async.wait_group 2;" ::: "memory")
#define CP_WAIT_0() asm volatile("cp.async.wait_group 0;" ::: "memory")

// ---------------------------------------------------------------------------
// Kernel 1: fused rowsum + adj f32->fp16 convert + per-row x scaling.
// ---------------------------------------------------------------------------
__global__ void rowsum_convert_kernel(const float* __restrict__ adj,
                                      const float* __restrict__ x) {
    const int row = blockIdx.x * blockDim.y + threadIdx.y;
    const int lane = threadIdx.x;
    const float4* p = reinterpret_cast<const float4*>(adj + (size_t)row * NN);
    uint2* hout = reinterpret_cast<uint2*>(g_adjh + (size_t)row * NN);
    float sum = 0.0f;
#pragma unroll 8
    for (int i = lane; i < NN / 4; i += 32) {
        float4 v = __ldcs(p + i);
        sum += (v.x + v.y) + (v.z + v.w);
        __half2 h0 = __floats2half2_rn(v.x, v.y);
        __half2 h1 = __floats2half2_rn(v.z, v.w);
        uint2 u;
        u.x = *reinterpret_cast<uint32_t*>(&h0);
        u.y = *reinterpret_cast<uint32_t*>(&h1);
        __stcs(hout + i, u);
    }
#pragma unroll
    for (int o = 16; o > 0; o >>= 1) sum += __shfl_xor_sync(0xffffffffu, sum, o);
    const float s = rsqrtf(__shfl_sync(0xffffffffu, sum, 0) + 1.0f);
    if (lane == 0) g_s[row] = s;

    const float4* xp = reinterpret_cast<const float4*>(x + (size_t)row * CC);
    uint2* xo = reinterpret_cast<uint2*>(g_xsh + (size_t)row * CC);
#pragma unroll
    for (int i = lane; i < CC / 4; i += 32) {
        float4 v = xp[i];
        __half2 h0 = __floats2half2_rn(s * v.x, s * v.y);
        __half2 h1 = __floats2half2_rn(s * v.z, s * v.w);
        uint2 u;
        u.x = *reinterpret_cast<uint32_t*>(&h0);
        u.y = *reinterpret_cast<uint32_t*>(&h1);
        xo[i] = u;
    }
}

// ---------------------------------------------------------------------------
// prep_w: convert w -> fp16, and reset g_done (runs first in the stream)
// ---------------------------------------------------------------------------
__global__ void prep_w_kernel(const float* __restrict__ w) {
    if (blockIdx.x == 0 && threadIdx.x < 64) g_done[threadIdx.x] = 0;
    const int idx = blockIdx.x * 256 + threadIdx.x;   // over CC*CC/4 float4s
    float4 v = reinterpret_cast<const float4*>(w)[idx];
    __half2 h0 = __floats2half2_rn(v.x, v.y);
    __half2 h1 = __floats2half2_rn(v.z, v.w);
    uint2 u;
    u.x = *reinterpret_cast<uint32_t*>(&h0);
    u.y = *reinterpret_cast<uint32_t*>(&h1);
    reinterpret_cast<uint2*>(g_wh)[idx] = u;
}

// ---------------------------------------------------------------------------
// Shared GEMM mainloop: 128x128 tile, BK=64, 4-stage cp.async, single barrier,
// reg-dbuf fragments, f32 accumulate. (R4 champion structure.)
// ---------------------------------------------------------------------------
constexpr int BM = 128, BN = 128, BK = 64, STAGES = 4;
constexpr int APAD = 72;
constexpr int BPAD = 136;
constexpr int A_HALVES = BM * APAD;        // 9216
constexpr int B_HALVES = BK * BPAD;        // 8704
constexpr int STAGE_BYTES = (A_HALVES + B_HALVES) * 2;   // 35840
constexpr int SMEM_BYTES = STAGES * STAGE_BYTES;          // 143360

__device__ __forceinline__ void gemm_mainloop(
    const __half* __restrict__ gA, size_t kA,
    const __half* __restrict__ gB, int k_iters,
    uint32_t sb, uint32_t sAo, uint32_t sBo, const char* smem,
    int wm, int wn,
    wmma::fragment<wmma::accumulator, 16, 16, 16, float> (&acc)[2][4]) {

    auto load_stage = [&](int kt, int s) {
        const uint32_t st = sb + s * STAGE_BYTES;
        const __half* a = gA + (size_t)kt * BK;
        const __half* b = gB + (size_t)kt * BK * CC;
#pragma unroll
        for (int r = 0; r < 4; r++)
            cpa16(st + sAo + r * (32 * APAD * 2), a + (size_t)(r * 32) * kA);
#pragma unroll
        for (int r = 0; r < 4; r++)
            cpa16(st + sBo + r * (16 * BPAD * 2), b + (size_t)(r * 16) * CC);
    };

#pragma unroll
    for (int s = 0; s < STAGES - 1; s++) {
        if (s < k_iters) load_stage(s, s);
        CP_COMMIT();
    }

    for (int kt = 0; kt < k_iters; kt++) {
        CP_WAIT_2();
        __syncthreads();   // protects slot (kt-1)&3 rewrite below

        const int nk = kt + STAGES - 1;
        if (nk < k_iters) load_stage(nk, nk & 3);
        CP_COMMIT();

        const __half* Ap = reinterpret_cast<const __half*>(smem + (kt & 3) * STAGE_BYTES);
        const __half* Bp = Ap + A_HALVES;

        wmma::fragment<wmma::matrix_a, 16, 16, 16, __half, wmma::row_major> af[2][2];
        wmma::fragment<wmma::matrix_b, 16, 16, 16, __half, wmma::row_major> bf[2][4];
#pragma unroll
        for (int i = 0; i < 2; i++)
            wmma::load_matrix_sync(af[0][i], Ap + (wm * 32 + i * 16) * APAD, APAD);
#pragma unroll
        for (int j = 0; j < 4; j++)
            wmma::load_matrix_sync(bf[0][j], Bp + wn * 64 + j * 16, BPAD);

#pragma unroll
        for (int ks = 0; ks < 4; ks++) {
            const int cu = ks & 1, nx = cu ^ 1;
            if (ks < 3) {
#pragma unroll
                for (int i = 0; i < 2; i++)
                    wmma::load_matrix_sync(af[nx][i],
                        Ap + (wm * 32 + i * 16) * APAD + (ks + 1) * 16, APAD);
#pragma unroll
                for (int j = 0; j < 4; j++)
                    wmma::load_matrix_sync(bf[nx][j],
                        Bp + ((ks + 1) * 16) * BPAD + wn * 64 + j * 16, BPAD);
            }
#pragma unroll
            for (int i = 0; i < 2; i++)
#pragma unroll
                for (int j = 0; j < 4; j++)
                    wmma::mma_sync(acc[i][j], af[cu][i], bf[cu][j], acc[i][j]);
        }
    }
    __syncthreads();   // all MMA smem reads done before smem reuse
}

// ---------------------------------------------------------------------------
// Fused kernel: phase 1 = t-tile (adjh @ xsh) -> a2h; handshake with sibling
// CTA; phase 2 = out-tile (a2h @ wh) with ELU. 128 CTAs, all co-resident.
// ---------------------------------------------------------------------------
__global__ __launch_bounds__(256, 1)
void gcn_fused(const float* __restrict__ xin, float* __restrict__ outp) {
    extern __shared__ char smem[];
    const uint32_t sb = smem_u32(smem);
    const int tid = threadIdx.x;
    const int warp = tid >> 5;
    const int wm = warp & 3;     // 0..3 along M
    const int wn = warp >> 2;    // 0..1 along N
    const int m0 = blockIdx.y * BM;
    const int n0 = blockIdx.x * BN;

    const int arr = tid >> 3, arc = (tid & 7) * 8;
    const int brr = tid >> 4, brc = (tid & 15) * 8;
    const uint32_t sAo = (arr * APAD + arc) * 2;
    const uint32_t sBo = A_HALVES * 2 + (brr * BPAD + brc) * 2;

    wmma::fragment<wmma::accumulator, 16, 16, 16, float> acc[2][4];
#pragma unroll
    for (int i = 0; i < 2; i++)
#pragma unroll
        for (int j = 0; j < 4; j++) wmma::fill_fragment(acc[i][j], 0.0f);

    // ================= phase 1: t = adjh @ xsh =================
    gemm_mainloop(g_adjh + (size_t)(m0 + arr) * NN + arc, NN,
                  g_xsh + (size_t)brr * CC + n0 + brc, NN / BK,
                  sb, sAo, sBo, smem, wm, wn, acc);

    // epilogue 1: a2h = fp16( s_i * (t + s_i * x) ), via f32 smem staging
    float* stg = reinterpret_cast<float*>(smem);   // 128 x 132
#pragma unroll
    for (int i = 0; i < 2; i++)
#pragma unroll
        for (int j = 0; j < 4; j++)
            wmma::store_matrix_sync(stg + (wm * 32 + i * 16) * 132 + wn * 64 + j * 16,
                                    acc[i][j], 132, wmma::mem_row_major);
    __syncthreads();

    {
        const int r = tid >> 1;
        const int c0 = (tid & 1) * 64;
        const int grow = m0 + r;
        const float sA = g_s[grow];
#pragma unroll
        for (int c = 0; c < 64; c += 4) {
            float4 v = *reinterpret_cast<const float4*>(stg + r * 132 + c0 + c);
            const int gcol = n0 + c0 + c;
            const float4 xv = *reinterpret_cast<const float4*>(xin + (size_t)grow * CC + gcol);
            __half2 h0 = __floats2half2_rn(sA * (v.x + sA * xv.x), sA * (v.y + sA * xv.y));
            __half2 h1 = __floats2half2_rn(sA * (v.z + sA * xv.z), sA * (v.w + sA * xv.w));
            uint2 u;
            u.x = *reinterpret_cast<uint32_t*>(&h0);
            u.y = *reinterpret_cast<uint32_t*>(&h1);
            *reinterpret_cast<uint2*>(&g_a2h[(size_t)grow * CC + gcol]) = u;
        }
    }

    // ================= handshake with sibling CTA (other n-half) =========
    __threadfence();       // per-thread: a2h stores visible at device scope
    __syncthreads();       // all threads' fences done
    if (tid == 0) {
        atomicAdd(&g_done[blockIdx.y], 1);
        while (atomicAdd(&g_done[blockIdx.y], 0) < 2) __nanosleep(64);
    }
    __syncthreads();
    __threadfence();       // acquire side
    CP_WAIT_0();           // drain any (empty) trailing cp.async groups

    // ================= phase 2: out = ELU( a2h @ wh ) =================
#pragma unroll
    for (int i = 0; i < 2; i++)
#pragma unroll
        for (int j = 0; j < 4; j++) wmma::fill_fragment(acc[i][j], 0.0f);

    gemm_mainloop(g_a2h + (size_t)(m0 + arr) * CC + arc, CC,
                  g_wh + (size_t)brr * CC + n0 + brc, CC / BK,
                  sb, sAo, sBo, smem, wm, wn, acc);

    // epilogue 2: ELU on fragments, direct store to out
#pragma unroll
    for (int i = 0; i < 2; i++)
#pragma unroll
        for (int j = 0; j < 4; j++) {
#pragma unroll
            for (int e = 0; e < 8; e++) {
                float v = acc[i][j].x[e];
                acc[i][j].x[e] = (v > 0.0f) ? v : expm1f(v);
            }
            const int r = m0 + wm * 32 + i * 16;
            const int c = n0 + wn * 64 + j * 16;
            wmma::store_matrix_sync(&outp[(size_t)r * CC + c], acc[i][j], CC,
                                    wmma::mem_row_major);
        }
}

// ---------------------------------------------------------------------------
extern "C" void kernel_launch(void* const* d_in, const int* in_sizes, int n_in,
                              void* d_out, int out_size) {
    const float *x = nullptr, *adj = nullptr, *w = nullptr;
    for (int i = 0; i < n_in; i++) {
        if (in_sizes[i] == NN * NN) adj = (const float*)d_in[i];
        else if (in_sizes[i] == NN * CC) x = (const float*)d_in[i];
        else if (in_sizes[i] == CC * CC) w = (const float*)d_in[i];
    }
    float* out = (float*)d_out;

    cudaFuncSetAttribute(gcn_fused, cudaFuncAttributeMaxDynamicSharedMemorySize, SMEM_BYTES);

    prep_w_kernel<<<CC * CC / 4 / 256, 256>>>(w);            // also resets g_done
    rowsum_convert_kernel<<<NN / 8, dim3(32, 8)>>>(adj, x);  // s + adjh + xsh
    // 128 CTAs, 1/SM, all co-resident (wave 1) -> inter-CTA handshake is safe.
    // blockIdx.x = n-half (fast) so sibling pairs are adjacent for L2 dedup.
    gcn_fused<<<dim3(2, 64), 256, SMEM_BYTES>>>(x, out);
}